// round 10
// baseline (speedup 1.0000x reference)
#include <cuda_runtime.h>
#include <cstdint>

#define N_NODES 50000
#define N_EDGES 800000
#define D 256

#define BM 128
#define BN 128
#define BK 16
#define GEMM_MBLKS 391            // ceil(50000/128)
#define GEMM_CTAS (2 * GEMM_MBLKS)
#define CONV_BLKS ((N_EDGES + 255) / 256)

// ---------------- scratch (device globals; no allocations) ----------------
__device__ int   g_is64;
__device__ int   g_esrc[N_EDGES];
__device__ int   g_edst[N_EDGES];
__device__ int   g_deg[N_NODES];
__device__ int   g_rowptr[N_NODES + 1];
__device__ int   g_cursor[N_NODES];
__device__ int   g_srcs[N_EDGES];
__device__ int   g_eid[N_EDGES];
__device__ float g_bufA[N_NODES * D];   // agg scratch, later A_pre
__device__ float g_bufB[N_NODES * D];   // Gr, h1, later B_pre
__device__ float g_bufC[N_NODES * D];   // h2

__device__ __forceinline__ float* selbuf(int s) {
    if (s == 0) return g_bufA;
    if (s == 1) return g_bufB;
    if (s == 2) return g_bufC;
    return nullptr;
}

// ---------------- detect dtype + zero degrees (fused) ----------------
__global__ void detect_zero_kernel(const int* __restrict__ ei32) {
    int i = blockIdx.x * blockDim.x + threadIdx.x;
    if (i < N_NODES) g_deg[i] = 0;
    if (i == 0) {
        int allzero = 1;
        for (int j = 1; j < 256; j += 2) {
            if (ei32[j] != 0) { allzero = 0; break; }
        }
        g_is64 = allzero;
    }
}

// ---------------- tf32 GEMM device body ----------------
__device__ __forceinline__ uint32_t f2tf32(float f) {
    uint32_t r;
    asm("cvt.rna.tf32.f32 %0, %1;" : "=r"(r) : "f"(f));
    return r;
}

__device__ __forceinline__ uint4 cvt4(float4 v) {
    uint4 r;
    r.x = f2tf32(v.x); r.y = f2tf32(v.y); r.z = f2tf32(v.z); r.w = f2tf32(v.w);
    return r;
}

__device__ __forceinline__ void mma_tf32(float* c, uint32_t a0, uint32_t a1,
                                         uint32_t a2, uint32_t a3,
                                         uint32_t b0, uint32_t b1) {
    asm volatile(
        "mma.sync.aligned.m16n8k8.row.col.f32.tf32.tf32.f32 "
        "{%0,%1,%2,%3}, {%4,%5,%6,%7}, {%8,%9}, {%0,%1,%2,%3};"
        : "+f"(c[0]), "+f"(c[1]), "+f"(c[2]), "+f"(c[3])
        : "r"(a0), "r"(a1), "r"(a2), "r"(a3), "r"(b0), "r"(b1));
}

// C[m0:m0+128, n0:n0+128] = act(A1@W1 (+ A2@W2) (+ bias) (+ Cold))
// K = 256, row-major, row stride 256. 256 threads.
template <bool DUAL, bool RELU, bool ACC>
__device__ __forceinline__ void gemm_body(
    const float* __restrict__ A1, const float* __restrict__ W1,
    const float* __restrict__ A2, const float* __restrict__ W2,
    const float* __restrict__ bias, float* __restrict__ C,
    int m0, int n0) {
    __shared__ uint32_t As[2][BM][BK + 4];    // stride 20: conflict-free
    __shared__ uint32_t Ws[2][BK][BN + 8];    // stride 136: conflict-free

    const int tid = threadIdx.x;
    const int lane = tid & 31;
    const int warp = tid >> 5;
    const int wm = warp & 3;
    const int wn = warp >> 2;

    const int itersPerPass = 256 / BK;           // 16
    const int total = DUAL ? 2 * itersPerPass : itersPerPass;

    float acc[2][8][4];
#pragma unroll
    for (int i = 0; i < 2; i++)
#pragma unroll
        for (int j = 0; j < 8; j++)
#pragma unroll
            for (int r = 0; r < 4; r++) acc[i][j][r] = 0.f;

    const int ar0 = tid >> 2, ac0 = (tid & 3) * 4;
    const int ar1 = (tid + 256) >> 2;
    const int wk0 = tid >> 5, wc0 = (tid & 31) * 4;
    const int wk1 = (tid + 256) >> 5;

    auto loadA = [&](const float* A, int kk, float4& v0, float4& v1) {
        int gm0 = m0 + ar0, gm1 = m0 + ar1;
        v0 = (gm0 < N_NODES) ? *(const float4*)(A + (size_t)gm0 * 256 + kk + ac0)
                             : make_float4(0.f, 0.f, 0.f, 0.f);
        v1 = (gm1 < N_NODES) ? *(const float4*)(A + (size_t)gm1 * 256 + kk + ac0)
                             : make_float4(0.f, 0.f, 0.f, 0.f);
    };
    auto loadW = [&](const float* W, int kk, float4& v0, float4& v1) {
        v0 = *(const float4*)(W + (size_t)(kk + wk0) * 256 + n0 + wc0);
        v1 = *(const float4*)(W + (size_t)(kk + wk1) * 256 + n0 + wc0);
    };
    auto storeTile = [&](int buf, const float4& a0v, const float4& a1v,
                         const float4& w0v, const float4& w1v) {
        *(uint4*)&As[buf][ar0][ac0] = cvt4(a0v);
        *(uint4*)&As[buf][ar1][ac0] = cvt4(a1v);
        *(uint4*)&Ws[buf][wk0][wc0] = cvt4(w0v);
        *(uint4*)&Ws[buf][wk1][wc0] = cvt4(w1v);
    };

    {
        float4 a0v, a1v, w0v, w1v;
        loadA(A1, 0, a0v, a1v);
        loadW(W1, 0, w0v, w1v);
        storeTile(0, a0v, a1v, w0v, w1v);
    }
    __syncthreads();

    const int mbase = wm * 32;
    const int nbase = wn * 64;
    const int fr = lane >> 2;
    const int fc = lane & 3;

    for (int it = 0; it < total; it++) {
        int buf = it & 1;
        float4 pa0, pa1, pw0, pw1;
        bool more = (it + 1) < total;
        if (more) {
            int nit = it + 1;
            const float* A = (DUAL && nit >= itersPerPass) ? A2 : A1;
            const float* W = (DUAL && nit >= itersPerPass) ? W2 : W1;
            int kk = (nit & (itersPerPass - 1)) * BK;
            loadA(A, kk, pa0, pa1);
            loadW(W, kk, pw0, pw1);
        }

#pragma unroll
        for (int ks = 0; ks < 2; ks++) {
            int kk = ks * 8;
            uint32_t af[2][4];
#pragma unroll
            for (int mt = 0; mt < 2; mt++) {
                int r = mbase + mt * 16 + fr;
                af[mt][0] = As[buf][r][kk + fc];
                af[mt][1] = As[buf][r + 8][kk + fc];
                af[mt][2] = As[buf][r][kk + fc + 4];
                af[mt][3] = As[buf][r + 8][kk + fc + 4];
            }
            uint32_t bf[8][2];
#pragma unroll
            for (int nt = 0; nt < 8; nt++) {
                int n = nbase + nt * 8 + fr;
                bf[nt][0] = Ws[buf][kk + fc][n];
                bf[nt][1] = Ws[buf][kk + fc + 4][n];
            }
#pragma unroll
            for (int mt = 0; mt < 2; mt++)
#pragma unroll
                for (int nt = 0; nt < 8; nt++)
                    mma_tf32(acc[mt][nt], af[mt][0], af[mt][1], af[mt][2], af[mt][3],
                             bf[nt][0], bf[nt][1]);
        }

        if (more) storeTile(buf ^ 1, pa0, pa1, pw0, pw1);
        __syncthreads();
    }

    // epilogue
#pragma unroll
    for (int mt = 0; mt < 2; mt++) {
#pragma unroll
        for (int nt = 0; nt < 8; nt++) {
            int gn = n0 + nbase + nt * 8 + 2 * fc;
            float b0 = bias ? bias[gn] : 0.f;
            float b1 = bias ? bias[gn + 1] : 0.f;
            int gm0 = m0 + mbase + mt * 16 + fr;
            int gm1 = gm0 + 8;
            float2 v0, v1;
            v0.x = acc[mt][nt][0] + b0; v0.y = acc[mt][nt][1] + b1;
            v1.x = acc[mt][nt][2] + b0; v1.y = acc[mt][nt][3] + b1;
            if (gm0 < N_NODES) {
                float* p = C + (size_t)gm0 * 256 + gn;
                if (ACC) { float2 o = *(float2*)p; v0.x += o.x; v0.y += o.y; }
                if (RELU) { v0.x = fmaxf(v0.x, 0.f); v0.y = fmaxf(v0.y, 0.f); }
                *(float2*)p = v0;
            }
            if (gm1 < N_NODES) {
                float* p = C + (size_t)gm1 * 256 + gn;
                if (ACC) { float2 o = *(float2*)p; v1.x += o.x; v1.y += o.y; }
                if (RELU) { v1.x = fmaxf(v1.x, 0.f); v1.y = fmaxf(v1.y, 0.f); }
                *(float2*)p = v1;
            }
        }
    }
}

// ---------------- GEMM kernel wrappers ----------------
template <bool DUAL, bool RELU, bool ACC>
__global__ __launch_bounds__(256, 2)
void gemm_kernel(const float* __restrict__ A1ext, int a1_sel,
                 const float* __restrict__ W1,
                 const float* __restrict__ A2ext, int a2_sel,
                 const float* __restrict__ W2,
                 const float* __restrict__ bias, int c_sel) {
    const float* A1 = A1ext ? A1ext : selbuf(a1_sel);
    const float* A2 = DUAL ? (A2ext ? A2ext : selbuf(a2_sel)) : nullptr;
    gemm_body<DUAL, RELU, ACC>(A1, W1, A2, W2, bias, selbuf(c_sel),
                               blockIdx.y * BM, blockIdx.x * BN);
}

// merged edge precompute: blockIdx.x 0,1 -> bufA = h2@Wm1_top (no bias)
//                         blockIdx.x 2,3 -> bufB = h2@Wm1_bot + bm1
__global__ __launch_bounds__(256, 2)
void gemm_pre_kernel(const float* __restrict__ Wm1, const float* __restrict__ bm1) {
    int half = blockIdx.x >> 1;
    int n0 = (blockIdx.x & 1) * BN;
    const float* W = Wm1 + (size_t)half * 256 * 256;
    float* C = half ? g_bufB : g_bufA;
    const float* bias = half ? bm1 : nullptr;
    gemm_body<false, false, false>(g_bufC, W, nullptr, nullptr, bias, C,
                                   blockIdx.y * BM, n0);
}

// fused: blocks [0,GEMM_CTAS) -> bufB = x@W1r + b1l  (CSR-independent)
//        blocks [GEMM_CTAS, +CONV_BLKS) -> edge convert + degree count
__global__ __launch_bounds__(256, 2)
void fused_gemmR_convert_kernel(const float* __restrict__ x,
                                const float* __restrict__ W1r,
                                const float* __restrict__ b1l,
                                const void* __restrict__ ei) {
    if (blockIdx.x < GEMM_CTAS) {
        int m0 = (blockIdx.x >> 1) * BM;
        int n0 = (blockIdx.x & 1) * BN;
        gemm_body<false, false, false>(x, W1r, nullptr, nullptr, b1l, g_bufB, m0, n0);
    } else {
        int e = (blockIdx.x - GEMM_CTAS) * 256 + threadIdx.x;
        if (e < N_EDGES) {
            int s, d;
            if (g_is64) {
                const long long* p = (const long long*)ei;
                s = (int)p[e];
                d = (int)p[N_EDGES + e];
            } else {
                const int* p = (const int*)ei;
                s = p[e];
                d = p[N_EDGES + e];
            }
            g_esrc[e] = s;
            g_edst[e] = d;
            atomicAdd(&g_deg[d], 1);
        }
    }
}

// ---------------- CSR scan + fill ----------------
__global__ void scan_kernel() {
    __shared__ int sh[1024];
    const int CH = 49;
    int t = threadIdx.x;
    int base = t * CH;
    int s = 0;
    for (int i = 0; i < CH; i++) {
        int idx = base + i;
        if (idx < N_NODES) s += g_deg[idx];
    }
    sh[t] = s;
    __syncthreads();
    for (int o = 1; o < 1024; o <<= 1) {
        int v = (t >= o) ? sh[t - o] : 0;
        __syncthreads();
        sh[t] += v;
        __syncthreads();
    }
    int run = sh[t] - s;
    for (int i = 0; i < CH; i++) {
        int idx = base + i;
        if (idx < N_NODES) {
            g_rowptr[idx] = run;
            g_cursor[idx] = run;
            run += g_deg[idx];
        }
    }
    if (t == 0) g_rowptr[N_NODES] = N_EDGES;
}

__global__ void fill_kernel() {
    int e = blockIdx.x * blockDim.x + threadIdx.x;
    if (e < N_EDGES) {
        int pos = atomicAdd(&g_cursor[g_edst[e]], 1);
        g_srcs[pos] = g_esrc[e];
        g_eid[pos] = e;
    }
}

// ---------------- mean aggregation: one warp per node ----------------
__global__ void aggregate_kernel(const float* __restrict__ in_ext, int in_sel, int out_sel) {
    const float* in = in_ext ? in_ext : selbuf(in_sel);
    float* out = selbuf(out_sel);
    int gtid = blockIdx.x * blockDim.x + threadIdx.x;
    int node = gtid >> 5;
    int lane = gtid & 31;
    if (node >= N_NODES) return;
    int beg = g_rowptr[node], end = g_rowptr[node + 1];
    float4 acc0 = make_float4(0.f, 0.f, 0.f, 0.f);
    float4 acc1 = make_float4(0.f, 0.f, 0.f, 0.f);
    for (int p = beg; p < end; p++) {
        int s = g_srcs[p];
        const float4* ps = (const float4*)(in + (size_t)s * D);
        float4 a = ps[lane];
        float4 b = ps[lane + 32];
        acc0.x += a.x; acc0.y += a.y; acc0.z += a.z; acc0.w += a.w;
        acc1.x += b.x; acc1.y += b.y; acc1.z += b.z; acc1.w += b.w;
    }
    float inv = 1.f / fmaxf((float)(end - beg), 1.f);
    acc0.x *= inv; acc0.y *= inv; acc0.z *= inv; acc0.w *= inv;
    acc1.x *= inv; acc1.y *= inv; acc1.z *= inv; acc1.w *= inv;
    float4* po = (float4*)(out + (size_t)node * D);
    po[lane] = acc0;
    po[lane + 32] = acc1;
}

// ---------------- edge MLP, CSR order: one warp per DST node ----------------
__global__ void edge_kernel_csr(const float* __restrict__ Wm2,
                                const float* __restrict__ bm2,
                                float* __restrict__ out) {
    __shared__ __align__(16) float w0[256];
    __shared__ __align__(16) float w1[256];
    for (int i = threadIdx.x; i < 256; i += blockDim.x) {
        w0[i] = Wm2[i * 2 + 0];
        w1[i] = Wm2[i * 2 + 1];
    }
    __syncthreads();

    int gtid = blockIdx.x * blockDim.x + threadIdx.x;
    int node = gtid >> 5;
    int lane = gtid & 31;
    if (node >= N_NODES) return;

    int beg = g_rowptr[node], end = g_rowptr[node + 1];
    if (beg == end) return;

    const float4* pb = (const float4*)(g_bufB + (size_t)node * D);
    float4 b0 = pb[lane];
    float4 b1 = pb[lane + 32];

    const float4* w0f = (const float4*)w0;
    const float4* w1f = (const float4*)w1;
    float4 wa0 = w0f[lane], wa1 = w0f[lane + 32];
    float4 wb0 = w1f[lane], wb1 = w1f[lane + 32];

    float bias0 = bm2[0], bias1 = bm2[1];

    for (int p = beg; p < end; p++) {
        int s = g_srcs[p];
        int eid = g_eid[p];
        const float4* pa = (const float4*)(g_bufA + (size_t)s * D);
        float4 a0 = pa[lane];
        float4 a1 = pa[lane + 32];

        float4 v0, v1;
        v0.x = fmaxf(a0.x + b0.x, 0.f); v0.y = fmaxf(a0.y + b0.y, 0.f);
        v0.z = fmaxf(a0.z + b0.z, 0.f); v0.w = fmaxf(a0.w + b0.w, 0.f);
        v1.x = fmaxf(a1.x + b1.x, 0.f); v1.y = fmaxf(a1.y + b1.y, 0.f);
        v1.z = fmaxf(a1.z + b1.z, 0.f); v1.w = fmaxf(a1.w + b1.w, 0.f);

        float acc0 = 0.f, acc1 = 0.f;
        acc0 = fmaf(v0.x, wa0.x, acc0); acc0 = fmaf(v0.y, wa0.y, acc0);
        acc0 = fmaf(v0.z, wa0.z, acc0); acc0 = fmaf(v0.w, wa0.w, acc0);
        acc0 = fmaf(v1.x, wa1.x, acc0); acc0 = fmaf(v1.y, wa1.y, acc0);
        acc0 = fmaf(v1.z, wa1.z, acc0); acc0 = fmaf(v1.w, wa1.w, acc0);
        acc1 = fmaf(v0.x, wb0.x, acc1); acc1 = fmaf(v0.y, wb0.y, acc1);
        acc1 = fmaf(v0.z, wb0.z, acc1); acc1 = fmaf(v0.w, wb0.w, acc1);
        acc1 = fmaf(v1.x, wb1.x, acc1); acc1 = fmaf(v1.y, wb1.y, acc1);
        acc1 = fmaf(v1.z, wb1.z, acc1); acc1 = fmaf(v1.w, wb1.w, acc1);

#pragma unroll
        for (int o = 16; o > 0; o >>= 1) {
            acc0 += __shfl_xor_sync(0xFFFFFFFFu, acc0, o);
            acc1 += __shfl_xor_sync(0xFFFFFFFFu, acc1, o);
        }
        if (lane == 0) {
            float2 r;
            r.x = acc0 + bias0;
            r.y = acc1 + bias1;
            *(float2*)(out + (size_t)eid * 2) = r;
        }
    }
}

// ---------------- launch ----------------
extern "C" void kernel_launch(void* const* d_in, const int* in_sizes, int n_in,
                              void* d_out, int out_size) {
    const float* x   = (const float*)d_in[0];
    const void*  ei  = d_in[1];
    const float* W1l = (const float*)d_in[2];
    const float* b1l = (const float*)d_in[3];
    const float* W1r = (const float*)d_in[4];
    const float* W2l = (const float*)d_in[5];
    const float* b2l = (const float*)d_in[6];
    const float* W2r = (const float*)d_in[7];
    const float* Wm1 = (const float*)d_in[8];
    const float* bm1 = (const float*)d_in[9];
    const float* Wm2 = (const float*)d_in[10];
    const float* bm2 = (const float*)d_in[11];
    float* out = (float*)d_out;

    dim3 ggrid(2, GEMM_MBLKS);
    dim3 pgrid(4, GEMM_MBLKS);
    int aggBlocks = (N_NODES * 32 + 255) / 256;

    // dtype detect + zero degrees
    detect_zero_kernel<<<(N_NODES + 255) / 256, 256>>>((const int*)ei);

    // fused: Gr = x@W1r + b1l -> bufB  ||  edge convert + degree count
    fused_gemmR_convert_kernel<<<GEMM_CTAS + CONV_BLKS, 256>>>(x, W1r, b1l, ei);

    // CSR scan + fill
    scan_kernel<<<1, 1024>>>();
    fill_kernel<<<CONV_BLKS, 256>>>();

    // layer 1: agg(x) -> bufA ; bufB = relu(bufA@W1l + bufB)
    aggregate_kernel<<<aggBlocks, 256>>>(x, -1, 0);
    gemm_kernel<false, true, true><<<ggrid, 256>>>(nullptr, 0, W1l, nullptr, -1, nullptr, nullptr, 1);

    // layer 2: agg(h1) -> bufA ; bufC = relu(bufA@W2l + bufB@W2r + b2l)
    aggregate_kernel<<<aggBlocks, 256>>>(nullptr, 1, 0);
    gemm_kernel<true, true, false><<<ggrid, 256>>>(nullptr, 0, W2l, nullptr, 1, W2r, b2l, 2);

    // merged edge precompute: bufA = h2@Wm1_top ; bufB = h2@Wm1_bot + bm1
    gemm_pre_kernel<<<pgrid, 256>>>(Wm1, bm1);

    // edge MLP in CSR (dst-grouped) order
    edge_kernel_csr<<<aggBlocks, 256>>>(Wm2, bm2, out);
}